// round 1
// baseline (speedup 1.0000x reference)
#include <cuda_runtime.h>
#include <cuda_bf16.h>
#include <math.h>

#define BB 2
#define LL 512
#define HH 128
#define CC 49
#define NEGV 1000000000000.0f
#define NSM 148

// ---------------- device scratch (no allocation allowed) ----------------
__device__ float g_projI[BB * LL * HH];   // [(b*L+l)*H + h], Wh_b folded in
__device__ float g_projJ[BB * LL * HH];
__device__ float g_R[255 * HH];           // [d*H + h]

// ---------------- fast tanh: 1 - 2/(exp(2x)+1) ----------------
__device__ __forceinline__ float fast_tanh(float x) {
    float e, r;
    asm("ex2.approx.f32 %0, %1;" : "=f"(e) : "f"(x * 2.885390081777927f)); // 2*log2(e)
    asm("rcp.approx.f32 %0, %1;" : "=f"(r) : "f"(e + 1.0f));
    return fmaf(-2.0f, r, 1.0f);
}

// ---------------- prep kernel: proj_i / proj_j / R ----------------
// smem: Wsm[k][h] padded stride 129 (k=0..255, h=0..127) + xs[256]
#define PREP_SMEM ((256 * 129 + 256) * 4)

__global__ __launch_bounds__(256, 1)
void prep_kernel(const float* __restrict__ inputs,
                 const float* __restrict__ Wh_w,
                 const float* __restrict__ Wh_b,
                 const float* __restrict__ rel_pos)
{
    extern __shared__ float sm[];
    float* Wsm = sm;                 // 256*129
    float* xs  = sm + 256 * 129;     // 256
    const int tid = threadIdx.x;

    // load Wh_w (H=128 rows x 256 cols) transposed into Wsm[k][h]
    for (int idx = tid; idx < 128 * 256; idx += 256) {
        int h = idx >> 8;
        int k = idx & 255;
        Wsm[k * 129 + h] = Wh_w[idx];
    }
    __syncthreads();

    const int NROWS = BB * LL + 255;   // 1279
    for (int r = blockIdx.x; r < NROWS; r += gridDim.x) {
        if (r < BB * LL) {
            // proj row: x = inputs[r,:] + sinusoidal(l,:)
            int l = r & (LL - 1);
            if (tid < 128) {
                int k = tid;
                int i2 = k >> 1;
                double freq = exp(-(double)(2 * i2) / 128.0 * 9.210340371976184); // ln(1e4)
                double ang = (double)l * freq;
                float em = (k & 1) ? (float)cos(ang) : (float)sin(ang);
                xs[k] = inputs[r * 128 + k] + em;
            }
            __syncthreads();
            int h = tid & 127;
            int half = tid >> 7;                 // 0 -> proj_i, 1 -> proj_j
            float s = half ? 0.0f : Wh_b[h];
            const float* wb = Wsm + half * 128 * 129 + h;
            #pragma unroll 8
            for (int kk = 0; kk < 128; kk++) s += xs[kk] * wb[kk * 129];
            if (half) g_projJ[r * 128 + h] = s;
            else      g_projI[r * 128 + h] = s;
            __syncthreads();
        } else {
            // rel table row d: rel_pos[127, d, :], dot over full 256 k
            int d = r - BB * LL;
            const float* trow = rel_pos + (size_t)(127 * 512 + d) * 256;
            xs[tid] = trow[tid];
            __syncthreads();
            if (tid < 128) {
                int h = tid;
                float s = 0.0f;
                const float* wb = Wsm + h;
                #pragma unroll 8
                for (int k = 0; k < 256; k++) s += xs[k] * wb[k * 129];
                g_R[d * 128 + h] = s;
            }
            __syncthreads();
        }
    }
}

// ---------------- main kernel ----------------
// smem: WoT[128][52] + Wob[52] + R_T[128][255] + pjT[128][129] + pis[2][128]
#define WOT_OFF  0
#define WOB_OFF  (128 * 52)
#define RT_OFF   (WOB_OFF + 52)
#define PJT_OFF  (RT_OFF + 128 * 255)
#define PIS_OFF  (PJT_OFF + 128 * 129)
#define MAIN_SMEM ((PIS_OFF + 2 * 128) * 4)

#define NUNITS (BB * 4 * 256)   // b(2) * jtile(4) * ipair(256) = 2048

__global__ __launch_bounds__(256, 1)
void main_kernel(const float* __restrict__ mask,
                 const float* __restrict__ Wo_w,
                 const float* __restrict__ Wo_b,
                 float* __restrict__ out)
{
    extern __shared__ float sm[];
    float* WoT = sm + WOT_OFF;
    float* Wob = sm + WOB_OFF;
    float* R_T = sm + RT_OFF;
    float* pjT = sm + PJT_OFF;
    float* pis = sm + PIS_OFF;
    const int tid = threadIdx.x;

    // load Wo transposed [h][c], padded row 52 (16B aligned rows)
    for (int idx = tid; idx < CC * HH; idx += 256) {
        int c = idx >> 7;
        int h = idx & 127;
        WoT[h * 52 + c] = Wo_w[idx];
    }
    if (tid < CC) Wob[tid] = Wo_b[tid];
    // load full R transposed [h][d], stride 255 (odd -> conflict-free STS)
    for (int idx = tid; idx < 255 * 128; idx += 256) {
        int d = idx >> 7;
        int h = idx & 127;
        R_T[h * 255 + d] = g_R[idx];
    }

    // balanced contiguous unit range for this block
    int u0 = (int)(((long long)blockIdx.x * NUNITS) / gridDim.x);
    int u1 = (int)(((long long)(blockIdx.x + 1) * NUNITS) / gridDim.x);
    int prev_bjt = -1;

    for (int u = u0; u < u1; u++) {
        int ic = u & 255;
        int jt = (u >> 8) & 3;
        int b  = u >> 10;
        int i0 = ic * 2;
        int j0 = jt * 128;
        int bjt = (b << 2) | jt;

        __syncthreads();   // protect pjT/pis overwrite vs previous unit readers
        if (bjt != prev_bjt) {
            for (int idx = tid; idx < 128 * 128; idx += 256) {
                int jl = idx >> 7;
                int h  = idx & 127;
                pjT[h * 129 + jl] = g_projJ[(b * LL + j0 + jl) * HH + h];
            }
            prev_bjt = bjt;
        }
        {
            int il = tid >> 7;
            int h  = tid & 127;
            pis[il * 128 + h] = g_projI[(b * LL + i0 + il) * HH + h];
        }
        __syncthreads();

        int jl = tid & 127;
        int il = tid >> 7;
        int i = i0 + il;
        int j = j0 + jl;
        int d = j - i;
        d = d < -127 ? -127 : (d > 127 ? 127 : d);
        d += 127;

        float acc[49];
        #pragma unroll
        for (int c = 0; c < 49; c++) acc[c] = 0.0f;

        const float* pip = pis + il * 128;
        const float* pjp = pjT + jl;
        const float* rp  = R_T + d;

        #pragma unroll 2
        for (int h = 0; h < 128; h++) {
            float s = pip[h] + pjp[h * 129] + rp[h * 255];
            float t = fast_tanh(s);
            const float4* w4 = (const float4*)(WoT + h * 52);
            #pragma unroll
            for (int cc = 0; cc < 12; cc++) {
                float4 w = w4[cc];
                acc[cc * 4 + 0] = fmaf(t, w.x, acc[cc * 4 + 0]);
                acc[cc * 4 + 1] = fmaf(t, w.y, acc[cc * 4 + 1]);
                acc[cc * 4 + 2] = fmaf(t, w.z, acc[cc * 4 + 2]);
                acc[cc * 4 + 3] = fmaf(t, w.w, acc[cc * 4 + 3]);
            }
            acc[48] = fmaf(t, WoT[h * 52 + 48], acc[48]);
        }

        float mr = mask[b * LL + i];
        float mc = mask[b * LL + j];
        float addr_ = -NEGV * (1.0f - mr);
        float addc_ = -NEGV * (1.0f - mc);
        float trisub = (j < i) ? NEGV : 0.0f;
        float* ob = out + (size_t)b * CC * LL * LL + (size_t)i * LL + j;
        #pragma unroll
        for (int c = 0; c < 49; c++) {
            float v = acc[c] + Wob[c];
            v = v * mr + addr_;
            v = v * mc + addc_;
            v -= trisub;
            ob[(size_t)c * LL * LL] = v;
        }
    }
}

// ---------------- launch ----------------
extern "C" void kernel_launch(void* const* d_in, const int* in_sizes, int n_in,
                              void* d_out, int out_size)
{
    const float* inputs = (const float*)d_in[0];
    const float* mask   = (const float*)d_in[1];
    const float* Wh_w   = (const float*)d_in[2];
    const float* Wh_b   = (const float*)d_in[3];
    const float* Wo_w   = (const float*)d_in[4];
    const float* Wo_b   = (const float*)d_in[5];
    const float* rel    = (const float*)d_in[6];
    float* out = (float*)d_out;

    cudaFuncSetAttribute(prep_kernel, cudaFuncAttributeMaxDynamicSharedMemorySize, PREP_SMEM);
    cudaFuncSetAttribute(main_kernel, cudaFuncAttributeMaxDynamicSharedMemorySize, MAIN_SMEM);

    prep_kernel<<<NSM, 256, PREP_SMEM>>>(inputs, Wh_w, Wh_b, rel);
    main_kernel<<<NSM, 256, MAIN_SMEM>>>(mask, Wo_w, Wo_b, out);
}

// round 4
// speedup vs baseline: 3.1493x; 3.1493x over previous
#include <cuda_runtime.h>
#include <cuda_bf16.h>
#include <math.h>
#include <stdint.h>

#define BB 2
#define LL 512
#define HH 128
#define CC 49
#define NEGV 1000000000000.0f
#define NSM 148
#define NTILES (8 * 512)      // bjt(8) * i(512)
#define NBLK 7                // c padded to 56

// ---------------- device scratch ----------------
__device__ float          g_projI[BB * LL * HH];   // f32, Wh_b folded
__device__ __nv_bfloat16  g_pjh[BB * LL * HH];     // proj_j bf16
__device__ __nv_bfloat16  g_Rh[255 * HH];          // rel proj bf16

__device__ __forceinline__ float tanh_fast(float x) {
    float t;
    asm("tanh.approx.f32 %0, %1;" : "=f"(t) : "f"(x));
    return t;
}

__device__ __forceinline__ uint32_t pack_bf16x2(float lo, float hi) {
    uint32_t v;
    asm("cvt.rn.satfinite.bf16x2.f32 %0, %1, %2;" : "=r"(v) : "f"(hi), "f"(lo));
    return v;
}

__device__ __forceinline__ float bflo(uint32_t v) { return __uint_as_float(v << 16); }
__device__ __forceinline__ float bfhi(uint32_t v) { return __uint_as_float(v & 0xffff0000u); }

__device__ __forceinline__ void mma_bf16(float* c, uint32_t a0, uint32_t a1,
                                         uint32_t a2, uint32_t a3,
                                         uint32_t b0, uint32_t b1) {
    asm volatile(
        "mma.sync.aligned.m16n8k16.row.col.f32.bf16.bf16.f32 "
        "{%0,%1,%2,%3}, {%4,%5,%6,%7}, {%8,%9}, {%0,%1,%2,%3};"
        : "+f"(c[0]), "+f"(c[1]), "+f"(c[2]), "+f"(c[3])
        : "r"(a0), "r"(a1), "r"(a2), "r"(a3), "r"(b0), "r"(b1));
}

// ---------------- prep kernel (passed R1; bf16 pj/R outputs) ----------------
#define PREP_SMEM ((256 * 129 + 256) * 4)

__global__ __launch_bounds__(256, 1)
void prep_kernel(const float* __restrict__ inputs,
                 const float* __restrict__ Wh_w,
                 const float* __restrict__ Wh_b,
                 const float* __restrict__ rel_pos)
{
    extern __shared__ float sm[];
    float* Wsm = sm;                 // 256*129 (k-major, padded)
    float* xs  = sm + 256 * 129;
    const int tid = threadIdx.x;

    for (int idx = tid; idx < 128 * 256; idx += 256) {
        int h = idx >> 8;
        int k = idx & 255;
        Wsm[k * 129 + h] = Wh_w[idx];
    }
    __syncthreads();

    const int NROWS = BB * LL + 255;   // 1279
    for (int r = blockIdx.x; r < NROWS; r += gridDim.x) {
        if (r < BB * LL) {
            int l = r & (LL - 1);
            if (tid < 128) {
                int k = tid;
                int i2 = k >> 1;
                double freq = exp(-(double)(2 * i2) / 128.0 * 9.210340371976184);
                double ang = (double)l * freq;
                float em = (k & 1) ? (float)cos(ang) : (float)sin(ang);
                xs[k] = inputs[r * 128 + k] + em;
            }
            __syncthreads();
            int h = tid & 127;
            int half = tid >> 7;
            float s = half ? 0.0f : Wh_b[h];
            const float* wb = Wsm + half * 128 * 129 + h;
            #pragma unroll 8
            for (int kk = 0; kk < 128; kk++) s += xs[kk] * wb[kk * 129];
            if (half) g_pjh[r * 128 + h] = __float2bfloat16(s);
            else      g_projI[r * 128 + h] = s;
            __syncthreads();
        } else {
            int d = r - BB * LL;
            const float* trow = rel_pos + (size_t)(127 * 512 + d) * 256;
            xs[tid] = trow[tid];
            __syncthreads();
            if (tid < 128) {
                int h = tid;
                float s = 0.0f;
                const float* wb = Wsm + h;
                #pragma unroll 8
                for (int k = 0; k < 256; k++) s += xs[k] * wb[k * 129];
                g_Rh[d * 128 + h] = __float2bfloat16(s);
            }
            __syncthreads();
        }
    }
}

// ---------------- main kernel smem layout (bytes) ----------------
// rows padded to 272B (=68 words; 68 mod 32 = 4) -> all 32 lanes hit distinct banks
#define OFF_WOB  0                       // 64 f32
#define OFF_R    256                     // 255 * 272 = 69360
#define OFF_PJ   (256 + 255 * 272)       // 128 * 272 = 34816 (also Wo f32 staging, 32768)
#define SMEM_MAIN (OFF_PJ + 128 * 272 + 16)

__global__ __launch_bounds__(256, 1)
void main_kernel(const float* __restrict__ mask,
                 const float* __restrict__ Wo_w,
                 const float* __restrict__ Wo_b,
                 float* __restrict__ out)
{
    extern __shared__ char smc[];
    const int tid  = threadIdx.x;
    const int w    = tid >> 5;
    const int lane = tid & 31;
    const int gid  = lane >> 2;        // 0..7
    const int q2   = (lane & 3) << 1;  // 0,2,4,6

    // ---- stage: wob + Wo f32 (into PJ area) + R (padded) ----
    if (tid < 64) ((float*)(smc + OFF_WOB))[tid] = (tid < CC) ? Wo_b[tid] : 0.0f;
    for (int idx = tid; idx < 64 * 128; idx += 256) {
        int c = idx >> 7;
        ((float*)(smc + OFF_PJ))[idx] = (c < CC) ? Wo_w[idx] : 0.0f;
    }
    for (int idx = tid; idx < 255 * 16; idx += 256) {
        int row = idx >> 4;
        int ch  = idx & 15;
        *(uint4*)(smc + OFF_R + row * 272 + ch * 16) = ((const uint4*)g_Rh)[idx];
    }
    __syncthreads();

    // ---- build register-resident B fragments: b[n][k][0..1] ----
    // b0 = Wo[c = n*8+gid][h = k*16+q2, +1],  b1 = same with h+8
    uint32_t breg[NBLK][8][2];
    {
        const float* ws = (const float*)(smc + OFF_PJ);
        #pragma unroll
        for (int n = 0; n < NBLK; n++) {
            const int c = n * 8 + gid;
            #pragma unroll
            for (int k = 0; k < 8; k++) {
                const int h0 = k * 16 + q2;
                float2 f0 = *(const float2*)(ws + c * 128 + h0);
                float2 f1 = *(const float2*)(ws + c * 128 + h0 + 8);
                breg[n][k][0] = pack_bf16x2(f0.x, f0.y);
                breg[n][k][1] = pack_bf16x2(f1.x, f1.y);
            }
        }
    }
    __syncthreads();   // B built before PJ area is overwritten

    // ---- tile range ----
    const int u0 = (int)(((long long)blockIdx.x * NTILES) / gridDim.x);
    const int u1 = (int)(((long long)(blockIdx.x + 1) * NTILES) / gridDim.x);
    int prev_bjt = -1;

    // preload pi for first tile
    float2 piA[8], piB[8];
    {
        const int bjt = u0 >> 9, i = u0 & 511, b = bjt >> 2;
        const float* pb_ = g_projI + (((b << 9) + i) << 7);
        #pragma unroll
        for (int k = 0; k < 8; k++) {
            piA[k] = *(const float2*)(pb_ + k * 16 + q2);
            piB[k] = *(const float2*)(pb_ + k * 16 + q2 + 8);
        }
    }

    float acc[NBLK][4];
    #pragma unroll
    for (int n = 0; n < NBLK; n++)
        #pragma unroll
        for (int e = 0; e < 4; e++) acc[n][e] = 0.0f;

    for (int u = u0; u < u1; u++) {
        const int bjt = u >> 9;
        const int i   = u & 511;
        const int b   = bjt >> 2;
        const int j0  = (bjt & 3) << 7;

        if (bjt != prev_bjt) {
            __syncthreads();
            const uint4* src = (const uint4*)(g_pjh + ((b << 9) + j0) * 128);
            for (int idx = tid; idx < 128 * 16; idx += 256) {
                int row = idx >> 4;
                int ch  = idx & 15;
                *(uint4*)(smc + OFF_PJ + row * 272 + ch * 16) = src[idx];
            }
            prev_bjt = bjt;
            __syncthreads();
        }

        // row indices / rel offsets
        const int jl = (w << 4) + gid;      // tile-local j, row lo
        const int jh = jl + 8;
        const int jg_lo = j0 + jl;
        const int jg_hi = j0 + jh;
        int dlo = jg_lo - i; dlo = dlo < -127 ? -127 : (dlo > 127 ? 127 : dlo); dlo += 127;
        int dhi = jg_hi - i; dhi = dhi < -127 ? -127 : (dhi > 127 ? 127 : dhi); dhi += 127;

        const char* pj_lo = smc + OFF_PJ + jl * 272 + q2 * 2;
        const char* pj_hi = smc + OFF_PJ + jh * 272 + q2 * 2;
        const char* r_lo  = smc + OFF_R  + dlo * 272 + q2 * 2;
        const char* r_hi  = smc + OFF_R  + dhi * 272 + q2 * 2;

        // ---- gen A fragments + mma, per k-block ----
        #pragma unroll
        for (int k = 0; k < 8; k++) {
            const uint32_t plo0 = *(const uint32_t*)(pj_lo + k * 32);
            const uint32_t plo1 = *(const uint32_t*)(pj_lo + k * 32 + 16);
            const uint32_t phi0 = *(const uint32_t*)(pj_hi + k * 32);
            const uint32_t phi1 = *(const uint32_t*)(pj_hi + k * 32 + 16);
            const uint32_t rl0  = *(const uint32_t*)(r_lo + k * 32);
            const uint32_t rl1  = *(const uint32_t*)(r_lo + k * 32 + 16);
            const uint32_t rh0  = *(const uint32_t*)(r_hi + k * 32);
            const uint32_t rh1  = *(const uint32_t*)(r_hi + k * 32 + 16);

            float t0 = tanh_fast(piA[k].x + bflo(plo0) + bflo(rl0));
            float t1 = tanh_fast(piA[k].y + bfhi(plo0) + bfhi(rl0));
            float t2 = tanh_fast(piB[k].x + bflo(plo1) + bflo(rl1));
            float t3 = tanh_fast(piB[k].y + bfhi(plo1) + bfhi(rl1));
            float s0 = tanh_fast(piA[k].x + bflo(phi0) + bflo(rh0));
            float s1 = tanh_fast(piA[k].y + bfhi(phi0) + bfhi(rh0));
            float s2 = tanh_fast(piB[k].x + bflo(phi1) + bflo(rh1));
            float s3 = tanh_fast(piB[k].y + bfhi(phi1) + bfhi(rh1));

            const uint32_t a0 = pack_bf16x2(t0, t1);   // row lo, h0 pair
            const uint32_t a1 = pack_bf16x2(s0, s1);   // row hi, h0 pair
            const uint32_t a2 = pack_bf16x2(t2, t3);   // row lo, h1 pair
            const uint32_t a3 = pack_bf16x2(s2, s3);   // row hi, h1 pair

            #pragma unroll
            for (int n = 0; n < NBLK; n++)
                mma_bf16(acc[n], a0, a1, a2, a3, breg[n][k][0], breg[n][k][1]);
        }

        // ---- prefetch next tile's pi (hidden behind epilogue) ----
        if (u + 1 < u1) {
            const int bjtn = (u + 1) >> 9;
            const int in_  = (u + 1) & 511;
            const int bn   = bjtn >> 2;
            const float* pb_ = g_projI + (((bn << 9) + in_) << 7);
            #pragma unroll
            for (int k = 0; k < 8; k++) {
                piA[k] = *(const float2*)(pb_ + k * 16 + q2);
                piB[k] = *(const float2*)(pb_ + k * 16 + q2 + 8);
            }
        }

        // ---- epilogue: bias, masks, tril, store ----
        const float mr = mask[(b << 9) + i];
        const float mclo = mask[(b << 9) + jg_lo];
        const float mchi = mask[(b << 9) + jg_hi];
        const float addr_ = -NEGV * (1.0f - mr);
        const float adclo = -NEGV * (1.0f - mclo);
        const float adchi = -NEGV * (1.0f - mchi);
        const float trilo = (jg_lo < i) ? NEGV : 0.0f;
        const float trihi = (jg_hi < i) ? NEGV : 0.0f;
        float* ob = out + (size_t)b * CC * LL * LL + (size_t)i * LL;
        const float* wobp = (const float*)(smc + OFF_WOB);

        #pragma unroll
        for (int n = 0; n < NBLK; n++) {
            const int c0 = n * 8 + q2;
            const float2 wv = *(const float2*)(wobp + c0);
            float v0 = (acc[n][0] + wv.x) * mr + addr_;
            float v1 = (acc[n][1] + wv.y) * mr + addr_;
            float v2 = (acc[n][2] + wv.x) * mr + addr_;
            float v3 = (acc[n][3] + wv.y) * mr + addr_;
            v0 = v0 * mclo + adclo - trilo;
            v1 = v1 * mclo + adclo - trilo;
            v2 = v2 * mchi + adchi - trihi;
            v3 = v3 * mchi + adchi - trihi;
            if (c0 < CC) {
                ob[(size_t)c0 * (LL * LL) + jg_lo] = v0;
                ob[(size_t)c0 * (LL * LL) + jg_hi] = v2;
            }
            if (c0 + 1 < CC) {
                ob[(size_t)(c0 + 1) * (LL * LL) + jg_lo] = v1;
                ob[(size_t)(c0 + 1) * (LL * LL) + jg_hi] = v3;
            }
            acc[n][0] = 0.0f; acc[n][1] = 0.0f; acc[n][2] = 0.0f; acc[n][3] = 0.0f;
        }
    }
}

// ---------------- launch ----------------
extern "C" void kernel_launch(void* const* d_in, const int* in_sizes, int n_in,
                              void* d_out, int out_size)
{
    const float* inputs = (const float*)d_in[0];
    const float* mask   = (const float*)d_in[1];
    const float* Wh_w   = (const float*)d_in[2];
    const float* Wh_b   = (const float*)d_in[3];
    const float* Wo_w   = (const float*)d_in[4];
    const float* Wo_b   = (const float*)d_in[5];
    const float* rel    = (const float*)d_in[6];
    float* out = (float*)d_out;

    cudaFuncSetAttribute(prep_kernel, cudaFuncAttributeMaxDynamicSharedMemorySize, PREP_SMEM);
    cudaFuncSetAttribute(main_kernel, cudaFuncAttributeMaxDynamicSharedMemorySize, SMEM_MAIN);

    prep_kernel<<<NSM, 256, PREP_SMEM>>>(inputs, Wh_w, Wh_b, rel);
    main_kernel<<<NSM, 256, SMEM_MAIN>>>(mask, Wo_w, Wo_b, out);
}

// round 6
// speedup vs baseline: 3.3652x; 1.0686x over previous
#include <cuda_runtime.h>
#include <cuda_bf16.h>
#include <math.h>
#include <stdint.h>

#define BB 2
#define LL 512
#define HH 128
#define CC 49
#define NEGV 1000000000000.0f
#define NSM 148
#define NPAIRS 2048           // 4096 tiles in pairs; pair p -> tiles 2p, 2p+1
#define NBLK 7                // c padded to 56
#define NREG 2                // n-blocks kept in registers

// ---------------- device scratch ----------------
__device__ float          g_projI[BB * LL * HH];   // f32, Wh_b folded
__device__ __nv_bfloat16  g_pjh[BB * LL * HH];     // proj_j bf16
__device__ __nv_bfloat16  g_Rh[255 * HH];          // rel proj bf16

__device__ __forceinline__ float tanh_fast(float x) {
    float t;
    asm("tanh.approx.f32 %0, %1;" : "=f"(t) : "f"(x));
    return t;
}
__device__ __forceinline__ uint32_t pack_bf16x2(float lo, float hi) {
    uint32_t v;
    asm("cvt.rn.satfinite.bf16x2.f32 %0, %1, %2;" : "=r"(v) : "f"(hi), "f"(lo));
    return v;
}
__device__ __forceinline__ float bflo(uint32_t v) { return __uint_as_float(v << 16); }
__device__ __forceinline__ float bfhi(uint32_t v) { return __uint_as_float(v & 0xffff0000u); }

__device__ __forceinline__ void mma_bf16(float* c, uint32_t a0, uint32_t a1,
                                         uint32_t a2, uint32_t a3,
                                         uint32_t b0, uint32_t b1) {
    asm volatile(
        "mma.sync.aligned.m16n8k16.row.col.f32.bf16.bf16.f32 "
        "{%0,%1,%2,%3}, {%4,%5,%6,%7}, {%8,%9}, {%0,%1,%2,%3};"
        : "+f"(c[0]), "+f"(c[1]), "+f"(c[2]), "+f"(c[3])
        : "r"(a0), "r"(a1), "r"(a2), "r"(a3), "r"(b0), "r"(b1));
}

// ---------------- prep kernel (all-fp32 transcendentals) ----------------
#define PREP_SMEM ((256 * 129 + 256) * 4)

__global__ __launch_bounds__(256, 1)
void prep_kernel(const float* __restrict__ inputs,
                 const float* __restrict__ Wh_w,
                 const float* __restrict__ Wh_b,
                 const float* __restrict__ rel_pos)
{
    extern __shared__ float sm[];
    float* Wsm = sm;                 // 256*129 (k-major, padded)
    float* xs  = sm + 256 * 129;
    const int tid = threadIdx.x;

    for (int idx = tid; idx < 128 * 256; idx += 256) {
        int h = idx >> 8;
        int k = idx & 255;
        Wsm[k * 129 + h] = Wh_w[idx];
    }
    __syncthreads();

    const int NROWS = BB * LL + 255;   // 1279
    for (int r = blockIdx.x; r < NROWS; r += gridDim.x) {
        if (r < BB * LL) {
            int l = r & (LL - 1);
            if (tid < 128) {
                int k = tid;
                int i2 = k >> 1;
                float freq = exp2f(-(float)(2 * i2) * (13.287712379549449f / 128.0f));
                float ang = (float)l * freq;
                float em = (k & 1) ? cosf(ang) : sinf(ang);
                xs[k] = inputs[r * 128 + k] + em;
            }
            __syncthreads();
            int h = tid & 127;
            int half = tid >> 7;
            float s = half ? 0.0f : Wh_b[h];
            const float* wb = Wsm + half * 128 * 129 + h;
            #pragma unroll 8
            for (int kk = 0; kk < 128; kk++) s += xs[kk] * wb[kk * 129];
            if (half) g_pjh[r * 128 + h] = __float2bfloat16(s);
            else      g_projI[r * 128 + h] = s;
            __syncthreads();
        } else {
            int d = r - BB * LL;
            const float* trow = rel_pos + (size_t)(127 * 512 + d) * 256;
            xs[tid] = trow[tid];
            __syncthreads();
            if (tid < 128) {
                int h = tid;
                float s = 0.0f;
                const float* wb = Wsm + h;
                #pragma unroll 8
                for (int k = 0; k < 256; k++) s += xs[k] * wb[k * 129];
                g_Rh[d * 128 + h] = __float2bfloat16(s);
            }
            __syncthreads();
        }
    }
}

// ---------------- main kernel smem layout (bytes) ----------------
// pj/R rows: 64 bf16x2 words, PERMUTED within row: dest word k*8+2q+s holds
// orig word k*8+q+4s  (q=0..3, s=0..1). Row stride 272B -> conflict-free LDS.64.
#define OFF_WOB  0                         // 64 f32 = 256B
#define OFF_B    256                       // 63 slots * 256B (sparse k*8+n) = 16384 reserved
#define OFF_R    16640                     // 255 * 272 = 69360
#define OFF_PJ   86000                     // 128 * 272 = 34816
#define SMEM_MAIN (OFF_PJ + 128 * 272 + 16)

__global__ __launch_bounds__(512, 1)
void main_kernel(const float* __restrict__ mask,
                 const float* __restrict__ Wo_w,
                 const float* __restrict__ Wo_b,
                 float* __restrict__ out)
{
    extern __shared__ char smc[];
    const int tid  = threadIdx.x;
    const int w    = tid >> 5;
    const int lane = tid & 31;
    const int gid  = lane >> 2;        // mma row group 0..7
    const int q2   = (lane & 3) << 1;  // 0,2,4,6
    const int grp  = w >> 3;           // tile half: 0 -> tile 2p, 1 -> tile 2p+1
    const int wg   = w & 7;            // warp within group -> 16-row span

    // ---- stage wob ----
    if (tid < 64) ((float*)(smc + OFF_WOB))[tid] = (tid < CC) ? Wo_b[tid] : 0.0f;

    // ---- stage R table, permuted rows ----
    for (int idx = tid; idx < 255 * 16; idx += 512) {
        const int row = idx >> 4;
        const int t   = idx & 15;
        uint4 v = ((const uint4*)g_Rh)[idx];
        uint32_t* dst = (uint32_t*)(smc + OFF_R + row * 272);
        const int base = (t >> 1) * 8 + (t & 1);
        dst[base + 0] = v.x; dst[base + 2] = v.y;
        dst[base + 4] = v.z; dst[base + 6] = v.w;
    }

    // ---- build B fragments in smem for n=NREG..6 (and regs for n=0..NREG-1) ----
    // smem slot (k*8+n), k=0..7, n=0..6 (sparse over 0..62): 32 lanes * uint2
    for (int idx = w; idx < 64; idx += 16) {     // FIX: cover all k (slots 0..62)
        const int k = idx >> 3;
        const int n = idx & 7;
        if (n < NBLK) {
            const int c = n * 8 + gid;
            const int h0 = k * 16 + q2;
            float2 f0 = make_float2(0.f, 0.f), f1 = make_float2(0.f, 0.f);
            if (c < CC) {
                f0 = *(const float2*)(Wo_w + c * 128 + h0);
                f1 = *(const float2*)(Wo_w + c * 128 + h0 + 8);
            }
            uint2 bb = make_uint2(pack_bf16x2(f0.x, f0.y), pack_bf16x2(f1.x, f1.y));
            *(uint2*)(smc + OFF_B + (((k * 8 + n) * 32) + lane) * 8) = bb;
        }
    }
    uint32_t breg[NREG][8][2];
    #pragma unroll
    for (int n = 0; n < NREG; n++) {
        const int c = n * 8 + gid;           // <= 15, always < CC
        #pragma unroll
        for (int k = 0; k < 8; k++) {
            const int h0 = k * 16 + q2;
            float2 f0 = *(const float2*)(Wo_w + c * 128 + h0);
            float2 f1 = *(const float2*)(Wo_w + c * 128 + h0 + 8);
            breg[n][k][0] = pack_bf16x2(f0.x, f0.y);
            breg[n][k][1] = pack_bf16x2(f1.x, f1.y);
        }
    }
    __syncthreads();

    // ---- pair range ----
    const int p0 = (int)(((long long)blockIdx.x * NPAIRS) / gridDim.x);
    const int p1 = (int)(((long long)(blockIdx.x + 1) * NPAIRS) / gridDim.x);
    int prev_bjt = -1;

    float acc[NBLK][4];
    #pragma unroll
    for (int n = 0; n < NBLK; n++)
        #pragma unroll
        for (int e = 0; e < 4; e++) acc[n][e] = 0.0f;

    for (int p = p0; p < p1; p++) {
        const int bjt = p >> 8;              // = (2p+grp) >> 9
        const int u   = 2 * p + grp;
        const int i   = u & 511;
        const int b   = bjt >> 2;
        const int j0  = (bjt & 3) << 7;

        if (bjt != prev_bjt) {
            __syncthreads();
            const uint4* src = (const uint4*)(g_pjh + ((b << 9) + j0) * 128);
            for (int idx = tid; idx < 128 * 16; idx += 512) {
                const int row = idx >> 4;
                const int t   = idx & 15;
                uint4 v = src[idx];
                uint32_t* dst = (uint32_t*)(smc + OFF_PJ + row * 272);
                const int base = (t >> 1) * 8 + (t & 1);
                dst[base + 0] = v.x; dst[base + 2] = v.y;
                dst[base + 4] = v.z; dst[base + 6] = v.w;
            }
            prev_bjt = bjt;
            __syncthreads();
        }

        // row indices / rel offsets
        const int jl = (wg << 4) + gid;
        const int jh = jl + 8;
        const int jg_lo = j0 + jl;
        const int jg_hi = j0 + jh;
        int dlo = jg_lo - i; dlo = dlo < -127 ? -127 : (dlo > 127 ? 127 : dlo); dlo += 127;
        int dhi = jg_hi - i; dhi = dhi < -127 ? -127 : (dhi > 127 ? 127 : dhi); dhi += 127;

        const char* pj_lo = smc + OFF_PJ + jl * 272 + q2 * 4;
        const char* pj_hi = smc + OFF_PJ + jh * 272 + q2 * 4;
        const char* r_lo  = smc + OFF_R  + dlo * 272 + q2 * 4;
        const char* r_hi  = smc + OFF_R  + dhi * 272 + q2 * 4;
        const float* pirow = g_projI + (((b << 9) + i) << 7);

        #pragma unroll
        for (int k = 0; k < 8; k++) {
            const float2 piA = *(const float2*)(pirow + k * 16 + q2);
            const float2 piB = *(const float2*)(pirow + k * 16 + q2 + 8);
            const uint2 plo = *(const uint2*)(pj_lo + k * 32);
            const uint2 phi = *(const uint2*)(pj_hi + k * 32);
            const uint2 rlo = *(const uint2*)(r_lo + k * 32);
            const uint2 rhi = *(const uint2*)(r_hi + k * 32);

            float t0 = tanh_fast(piA.x + bflo(plo.x) + bflo(rlo.x));
            float t1 = tanh_fast(piA.y + bfhi(plo.x) + bfhi(rlo.x));
            float t2 = tanh_fast(piB.x + bflo(plo.y) + bflo(rlo.y));
            float t3 = tanh_fast(piB.y + bfhi(plo.y) + bfhi(rlo.y));
            float s0 = tanh_fast(piA.x + bflo(phi.x) + bflo(rhi.x));
            float s1 = tanh_fast(piA.y + bfhi(phi.x) + bfhi(rhi.x));
            float s2 = tanh_fast(piB.x + bflo(phi.y) + bflo(rhi.y));
            float s3 = tanh_fast(piB.y + bfhi(phi.y) + bfhi(rhi.y));

            const uint32_t a0 = pack_bf16x2(t0, t1);
            const uint32_t a1 = pack_bf16x2(s0, s1);
            const uint32_t a2 = pack_bf16x2(t2, t3);
            const uint32_t a3 = pack_bf16x2(s2, s3);

            #pragma unroll
            for (int n = 0; n < NREG; n++)
                mma_bf16(acc[n], a0, a1, a2, a3, breg[n][k][0], breg[n][k][1]);
            #pragma unroll
            for (int n = NREG; n < NBLK; n++) {
                const uint2 bb = *(const uint2*)(smc + OFF_B + (((k * 8 + n) * 32) + lane) * 8);
                mma_bf16(acc[n], a0, a1, a2, a3, bb.x, bb.y);
            }
        }

        // ---- epilogue: bias, masks, tril, store ----
        const float mr = mask[(b << 9) + i];
        const float mclo = mask[(b << 9) + jg_lo];
        const float mchi = mask[(b << 9) + jg_hi];
        const float addr_ = -NEGV * (1.0f - mr);
        const float adclo = -NEGV * (1.0f - mclo);
        const float adchi = -NEGV * (1.0f - mchi);
        const float trilo = (jg_lo < i) ? NEGV : 0.0f;
        const float trihi = (jg_hi < i) ? NEGV : 0.0f;
        float* ob = out + (size_t)b * CC * LL * LL + (size_t)i * LL;
        const float* wobp = (const float*)(smc + OFF_WOB);

        #pragma unroll
        for (int n = 0; n < NBLK; n++) {
            const int c0 = n * 8 + q2;
            const float2 wv = *(const float2*)(wobp + c0);
            float v0 = (acc[n][0] + wv.x) * mr + addr_;
            float v1 = (acc[n][1] + wv.y) * mr + addr_;
            float v2 = (acc[n][2] + wv.x) * mr + addr_;
            float v3 = (acc[n][3] + wv.y) * mr + addr_;
            v0 = v0 * mclo + adclo - trilo;
            v1 = v1 * mclo + adclo - trilo;
            v2 = v2 * mchi + adchi - trihi;
            v3 = v3 * mchi + adchi - trihi;
            if (c0 < CC) {
                ob[(size_t)c0 * (LL * LL) + jg_lo] = v0;
                ob[(size_t)c0 * (LL * LL) + jg_hi] = v2;
            }
            if (c0 + 1 < CC) {
                ob[(size_t)(c0 + 1) * (LL * LL) + jg_lo] = v1;
                ob[(size_t)(c0 + 1) * (LL * LL) + jg_hi] = v3;
            }
            acc[n][0] = 0.0f; acc[n][1] = 0.0f; acc[n][2] = 0.0f; acc[n][3] = 0.0f;
        }
    }
}

// ---------------- launch ----------------
extern "C" void kernel_launch(void* const* d_in, const int* in_sizes, int n_in,
                              void* d_out, int out_size)
{
    const float* inputs = (const float*)d_in[0];
    const float* mask   = (const float*)d_in[1];
    const float* Wh_w   = (const float*)d_in[2];
    const float* Wh_b   = (const float*)d_in[3];
    const float* Wo_w   = (const float*)d_in[4];
    const float* Wo_b   = (const float*)d_in[5];
    const float* rel    = (const float*)d_in[6];
    float* out = (float*)d_out;

    cudaFuncSetAttribute(prep_kernel, cudaFuncAttributeMaxDynamicSharedMemorySize, PREP_SMEM);
    cudaFuncSetAttribute(main_kernel, cudaFuncAttributeMaxDynamicSharedMemorySize, SMEM_MAIN);

    prep_kernel<<<NSM, 256, PREP_SMEM>>>(inputs, Wh_w, Wh_b, rel);
    main_kernel<<<NSM, 512, SMEM_MAIN>>>(mask, Wo_w, Wo_b, out);
}

// round 7
// speedup vs baseline: 4.3534x; 1.2937x over previous
#include <cuda_runtime.h>
#include <cuda_bf16.h>
#include <math.h>
#include <stdint.h>

#define BB 2
#define LL 512
#define HH 128
#define CC 49
#define NEGV 1000000000000.0f
#define NSM 148
#define NPAIRS 2048           // 4096 tiles in pairs; pair p -> tiles 2p, 2p+1
#define NBLK 7                // c padded to 56
#define NREG 2                // n-blocks kept in registers

// ---------------- device scratch (all bf16, PERMUTED rows) ----------------
// permuted word layout per 128-h row (64 bf16x2 words):
//   dest word 8k+2q+s  <-  orig word 8k+q+4s   (k=0..7, q=0..3, s=0..1)
__device__ __nv_bfloat16  g_piP[BB * LL * HH];   // proj_i (Wh_b folded)
__device__ __nv_bfloat16  g_pjh[BB * LL * HH];   // proj_j
__device__ __nv_bfloat16  g_Rh[255 * HH];        // rel proj

__device__ __forceinline__ int permh(int h) {
    int m = h >> 1;
    int dw = (m & ~7) | ((m & 3) << 1) | ((m >> 2) & 1);
    return (dw << 1) | (h & 1);
}
__device__ __forceinline__ uint32_t pack_bf16x2(float lo, float hi) {
    uint32_t v;
    asm("cvt.rn.satfinite.bf16x2.f32 %0, %1, %2;" : "=r"(v) : "f"(hi), "f"(lo));
    return v;
}
__device__ __forceinline__ uint32_t hadd2(uint32_t a, uint32_t b) {
    uint32_t d; asm("add.rn.bf16x2 %0, %1, %2;" : "=r"(d) : "r"(a), "r"(b)); return d;
}
__device__ __forceinline__ uint32_t tanh2(uint32_t a) {
    uint32_t d; asm("tanh.approx.bf16x2 %0, %1;" : "=r"(d) : "r"(a)); return d;
}
__device__ __forceinline__ void mma_bf16(float* c, uint32_t a0, uint32_t a1,
                                         uint32_t a2, uint32_t a3,
                                         uint32_t b0, uint32_t b1) {
    asm volatile(
        "mma.sync.aligned.m16n8k16.row.col.f32.bf16.bf16.f32 "
        "{%0,%1,%2,%3}, {%4,%5,%6,%7}, {%8,%9}, {%0,%1,%2,%3};"
        : "+f"(c[0]), "+f"(c[1]), "+f"(c[2]), "+f"(c[3])
        : "r"(a0), "r"(a1), "r"(a2), "r"(a3), "r"(b0), "r"(b1));
}

// ---------------- prep kernel v2: 512 threads, multi-row passes ----------------
// smem: Wsm[256][129] f32 (132096B) + xs[1056] f32 (4224B)
#define PREP_SMEM (256 * 129 * 4 + 1056 * 4)
#define NUNITS_PREP 576        // 512 input row-pairs + 64 rel groups-of-4

__global__ __launch_bounds__(512, 1)
void prep_kernel(const float* __restrict__ inputs,
                 const float* __restrict__ Wh_w,
                 const float* __restrict__ Wh_b,
                 const float* __restrict__ rel_pos)
{
    extern __shared__ float sm[];
    float* Wsm = sm;                  // [k_glob][h] stride 129
    float* xs  = sm + 256 * 129;      // up to 4*264 floats
    const int tid = threadIdx.x;

    // stage W transposed: Wsm[k][h] = Wh_w[h][k]
    for (int idx = tid; idx < 128 * 256; idx += 512) {
        int h = idx >> 8;
        int k = idx & 255;
        Wsm[k * 129 + h] = Wh_w[idx];
    }
    __syncthreads();

    for (int u = blockIdx.x; u < NUNITS_PREP; u += gridDim.x) {
        if (u < 512) {
            // input rows 2u, 2u+1
            const int r0 = u * 2;
            if (tid < 256) {
                int row = tid >> 7, k = tid & 127;
                int l = (r0 + row) & (LL - 1);
                int i2 = k >> 1;
                float freq = exp2f(-(float)(2 * i2) * (13.287712379549449f / 128.0f));
                float ang = (float)l * freq;
                float em = (k & 1) ? cosf(ang) : sinf(ang);
                xs[row * 132 + k] = inputs[(r0 + row) * 128 + k] + em;
            }
            __syncthreads();
            {
                int row  = tid >> 8;          // 0..1
                int half = (tid >> 7) & 1;    // 0: proj_i, 1: proj_j
                int h    = tid & 127;
                float s = half ? 0.0f : Wh_b[h];
                const float* wb = Wsm + half * 128 * 129 + h;
                const float* xr = xs + row * 132;
                #pragma unroll 8
                for (int kk = 0; kk < 128; kk++) s += xr[kk] * wb[kk * 129];
                const int r = r0 + row;
                if (half) g_pjh[r * 128 + permh(h)] = __float2bfloat16(s);
                else      g_piP[r * 128 + permh(h)] = __float2bfloat16(s);
            }
            __syncthreads();
        } else {
            // rel rows 4g..4g+3 (d<255)
            const int g = u - 512;
            for (int idx = tid; idx < 1024; idx += 512) {
                int row = idx >> 8, k = idx & 255;
                int d = g * 4 + row;
                xs[row * 264 + k] = (d < 255)
                    ? rel_pos[(size_t)(127 * 512 + d) * 256 + k] : 0.0f;
            }
            __syncthreads();
            {
                int row = tid >> 7;           // 0..3
                int h   = tid & 127;
                int d = g * 4 + row;
                float s = 0.0f;
                const float* xr = xs + row * 264;
                const float* wb = Wsm + h;
                #pragma unroll 8
                for (int k = 0; k < 256; k++) s += xr[k] * wb[k * 129];
                if (d < 255) g_Rh[d * 128 + permh(h)] = __float2bfloat16(s);
            }
            __syncthreads();
        }
    }
}

// ---------------- main kernel smem layout (bytes) ----------------
// pj/R rows: permuted, stride 288B (72 words): conflict-free LDS.64
// B: 20 dense slots (kp*5 + n-2), each 32 lanes x uint4 (k-pair packed)
#define ROWB 288
#define OFF_WOB  0                          // 64 f32 = 256B
#define OFF_B    256                        // 20*512 = 10240
#define OFF_R    10496                      // 255*288 = 73440
#define OFF_PJ   83936                      // 128*288 = 36864
#define SMEM_MAIN (OFF_PJ + 128 * ROWB + 16)

__global__ __launch_bounds__(512, 1)
void main_kernel(const float* __restrict__ mask,
                 const float* __restrict__ Wo_w,
                 const float* __restrict__ Wo_b,
                 float* __restrict__ out)
{
    extern __shared__ char smc[];
    const int tid  = threadIdx.x;
    const int w    = tid >> 5;
    const int lane = tid & 31;
    const int gid  = lane >> 2;        // mma row group 0..7
    const int q2   = (lane & 3) << 1;  // 0,2,4,6
    const int grp  = w >> 3;           // tile half: 0 -> tile 2p, 1 -> tile 2p+1
    const int wg   = w & 7;            // warp within group -> 16-row span

    // ---- stage wob ----
    if (tid < 64) ((float*)(smc + OFF_WOB))[tid] = (tid < CC) ? Wo_b[tid] : 0.0f;

    // ---- stage R table (straight copy, permuted in gmem) ----
    for (int idx = tid; idx < 255 * 16; idx += 512) {
        const int row = idx >> 4;
        const int t   = idx & 15;
        *(uint4*)(smc + OFF_R + row * ROWB + t * 16) = ((const uint4*)g_Rh)[idx];
    }

    // ---- stage B k-pair slots (n=2..6), warp-cooperative ----
    for (int s = w; s < 20; s += 16) {
        const int kp = s / 5;
        const int n  = (s % 5) + 2;
        const int c  = n * 8 + gid;
        uint32_t b00 = 0, b01 = 0, b10 = 0, b11 = 0;
        if (c < CC) {
            const float* wp = Wo_w + c * 128 + kp * 32 + q2;
            b00 = pack_bf16x2(wp[0],  wp[1]);
            b01 = pack_bf16x2(wp[8],  wp[9]);
            b10 = pack_bf16x2(wp[16], wp[17]);
            b11 = pack_bf16x2(wp[24], wp[25]);
        }
        *(uint4*)(smc + OFF_B + (s * 32 + lane) * 16) = make_uint4(b00, b01, b10, b11);
    }

    // ---- register-resident B for n=0,1 ----
    uint32_t breg[NREG][8][2];
    #pragma unroll
    for (int n = 0; n < NREG; n++) {
        const int c = n * 8 + gid;           // <= 15 < CC
        #pragma unroll
        for (int k = 0; k < 8; k++) {
            const int h0 = k * 16 + q2;
            float2 f0 = *(const float2*)(Wo_w + c * 128 + h0);
            float2 f1 = *(const float2*)(Wo_w + c * 128 + h0 + 8);
            breg[n][k][0] = pack_bf16x2(f0.x, f0.y);
            breg[n][k][1] = pack_bf16x2(f1.x, f1.y);
        }
    }
    __syncthreads();

    // ---- pair range ----
    const int p0 = (int)(((long long)blockIdx.x * NPAIRS) / gridDim.x);
    const int p1 = (int)(((long long)(blockIdx.x + 1) * NPAIRS) / gridDim.x);
    int prev_bjt = -1;

    float acc[NBLK][4];
    #pragma unroll
    for (int n = 0; n < NBLK; n++)
        #pragma unroll
        for (int e = 0; e < 4; e++) acc[n][e] = 0.0f;

    for (int p = p0; p < p1; p++) {
        const int bjt = p >> 8;
        const int u   = 2 * p + grp;
        const int i   = u & 511;
        const int b   = bjt >> 2;
        const int j0  = (bjt & 3) << 7;

        if (bjt != prev_bjt) {
            __syncthreads();
            const uint4* src = (const uint4*)(g_pjh + ((b << 9) + j0) * 128);
            for (int idx = tid; idx < 128 * 16; idx += 512) {
                const int row = idx >> 4;
                const int t   = idx & 15;
                *(uint4*)(smc + OFF_PJ + row * ROWB + t * 16) = src[idx];
            }
            prev_bjt = bjt;
            __syncthreads();
        }

        const int jl = (wg << 4) + gid;
        const int jh = jl + 8;
        const int jg_lo = j0 + jl;
        const int jg_hi = j0 + jh;
        int dlo = jg_lo - i; dlo = dlo < -127 ? -127 : (dlo > 127 ? 127 : dlo); dlo += 127;
        int dhi = jg_hi - i; dhi = dhi < -127 ? -127 : (dhi > 127 ? 127 : dhi); dhi += 127;

        const char* pjl_ = smc + OFF_PJ + jl * ROWB + q2 * 4;
        const char* pjh_ = smc + OFF_PJ + jh * ROWB + q2 * 4;
        const char* rl_  = smc + OFF_R  + dlo * ROWB + q2 * 4;
        const char* rh_  = smc + OFF_R  + dhi * ROWB + q2 * 4;
        const char* pip  = (const char*)g_piP + (size_t)((b << 9) + i) * 256 + q2 * 4;

        #pragma unroll
        for (int kp = 0; kp < 4; kp++) {
            const uint2 pi0 = *(const uint2*)(pip + kp * 64);
            const uint2 pi1 = *(const uint2*)(pip + kp * 64 + 32);
            const uint2 pl0 = *(const uint2*)(pjl_ + kp * 64);
            const uint2 pl1 = *(const uint2*)(pjl_ + kp * 64 + 32);
            const uint2 ph0 = *(const uint2*)(pjh_ + kp * 64);
            const uint2 ph1 = *(const uint2*)(pjh_ + kp * 64 + 32);
            const uint2 rl0 = *(const uint2*)(rl_ + kp * 64);
            const uint2 rl1 = *(const uint2*)(rl_ + kp * 64 + 32);
            const uint2 rh0 = *(const uint2*)(rh_ + kp * 64);
            const uint2 rh1 = *(const uint2*)(rh_ + kp * 64 + 32);

            // k0 = 2kp fragments
            const uint32_t a0 = tanh2(hadd2(hadd2(pi0.x, pl0.x), rl0.x));
            const uint32_t a1 = tanh2(hadd2(hadd2(pi0.x, ph0.x), rh0.x));
            const uint32_t a2 = tanh2(hadd2(hadd2(pi0.y, pl0.y), rl0.y));
            const uint32_t a3 = tanh2(hadd2(hadd2(pi0.y, ph0.y), rh0.y));
            // k1 = 2kp+1 fragments
            const uint32_t a4 = tanh2(hadd2(hadd2(pi1.x, pl1.x), rl1.x));
            const uint32_t a5 = tanh2(hadd2(hadd2(pi1.x, ph1.x), rh1.x));
            const uint32_t a6 = tanh2(hadd2(hadd2(pi1.y, pl1.y), rl1.y));
            const uint32_t a7 = tanh2(hadd2(hadd2(pi1.y, ph1.y), rh1.y));

            #pragma unroll
            for (int n = 0; n < NREG; n++) {
                mma_bf16(acc[n], a0, a1, a2, a3, breg[n][2 * kp][0], breg[n][2 * kp][1]);
                mma_bf16(acc[n], a4, a5, a6, a7, breg[n][2 * kp + 1][0], breg[n][2 * kp + 1][1]);
            }
            #pragma unroll
            for (int n = NREG; n < NBLK; n++) {
                const uint4 bb = *(const uint4*)(smc + OFF_B +
                                 ((kp * 5 + (n - 2)) * 32 + lane) * 16);
                mma_bf16(acc[n], a0, a1, a2, a3, bb.x, bb.y);
                mma_bf16(acc[n], a4, a5, a6, a7, bb.z, bb.w);
            }
        }

        // ---- epilogue: bias, masks, tril, store ----
        const float mr = mask[(b << 9) + i];
        const float mclo = mask[(b << 9) + jg_lo];
        const float mchi = mask[(b << 9) + jg_hi];
        const float addr_ = -NEGV * (1.0f - mr);
        const float adclo = -NEGV * (1.0f - mclo);
        const float adchi = -NEGV * (1.0f - mchi);
        const float trilo = (jg_lo < i) ? NEGV : 0.0f;
        const float trihi = (jg_hi < i) ? NEGV : 0.0f;
        float* ob = out + (size_t)b * CC * LL * LL + (size_t)i * LL;
        const float* wobp = (const float*)(smc + OFF_WOB);

        #pragma unroll
        for (int n = 0; n < NBLK; n++) {
            const int c0 = n * 8 + q2;
            const float2 wv = *(const float2*)(wobp + c0);
            float v0 = (acc[n][0] + wv.x) * mr + addr_;
            float v1 = (acc[n][1] + wv.y) * mr + addr_;
            float v2 = (acc[n][2] + wv.x) * mr + addr_;
            float v3 = (acc[n][3] + wv.y) * mr + addr_;
            v0 = v0 * mclo + adclo - trilo;
            v1 = v1 * mclo + adclo - trilo;
            v2 = v2 * mchi + adchi - trihi;
            v3 = v3 * mchi + adchi - trihi;
            if (c0 < CC) {
                ob[(size_t)c0 * (LL * LL) + jg_lo] = v0;
                ob[(size_t)c0 * (LL * LL) + jg_hi] = v2;
            }
            if (c0 + 1 < CC) {
                ob[(size_t)(c0 + 1) * (LL * LL) + jg_lo] = v1;
                ob[(size_t)(c0 + 1) * (LL * LL) + jg_hi] = v3;
            }
            acc[n][0] = 0.0f; acc[n][1] = 0.0f; acc[n][2] = 0.0f; acc[n][3] = 0.0f;
        }
    }
}

// ---------------- launch ----------------
extern "C" void kernel_launch(void* const* d_in, const int* in_sizes, int n_in,
                              void* d_out, int out_size)
{
    const float* inputs = (const float*)d_in[0];
    const float* mask   = (const float*)d_in[1];
    const float* Wh_w   = (const float*)d_in[2];
    const float* Wh_b   = (const float*)d_in[3];
    const float* Wo_w   = (const float*)d_in[4];
    const float* Wo_b   = (const float*)d_in[5];
    const float* rel    = (const float*)d_in[6];
    float* out = (float*)d_out;

    cudaFuncSetAttribute(prep_kernel, cudaFuncAttributeMaxDynamicSharedMemorySize, PREP_SMEM);
    cudaFuncSetAttribute(main_kernel, cudaFuncAttributeMaxDynamicSharedMemorySize, SMEM_MAIN);

    prep_kernel<<<NSM, 512, PREP_SMEM>>>(inputs, Wh_w, Wh_b, rel);
    main_kernel<<<NSM, 512, SMEM_MAIN>>>(mask, Wo_w, Wo_b, out);
}

// round 8
// speedup vs baseline: 4.6232x; 1.0620x over previous
#include <cuda_runtime.h>
#include <cuda_fp16.h>
#include <math.h>
#include <stdint.h>

#define BB 2
#define LL 512
#define HH 128
#define CC 49
#define NEGV 1000000000000.0f
#define NSM 148
#define NQUADS 1024           // 4096 tiles in quads: tile u = 4q + 2*grp + t
#define NBLK 7                // c padded to 56

// ---------------- device scratch (all f16, PERMUTED rows) ----------------
// permuted word layout per 128-h row (64 f16x2 words):
//   dest word 8k+2q+s  <-  orig word 8k+q+4s   (k=0..7, q=0..3, s=0..1)
__device__ __half  g_piP[BB * LL * HH];   // proj_i (Wh_b folded)
__device__ __half  g_pjh[BB * LL * HH];   // proj_j
__device__ __half  g_Rh[255 * HH];        // rel proj

__device__ __forceinline__ int permh(int h) {
    int m = h >> 1;
    int dw = (m & ~7) | ((m & 3) << 1) | ((m >> 2) & 1);
    return (dw << 1) | (h & 1);
}
__device__ __forceinline__ uint32_t pack_f16x2(float lo, float hi) {
    __half2 p = __floats2half2_rn(lo, hi);
    return *(uint32_t*)&p;
}
__device__ __forceinline__ uint32_t hadd2(uint32_t a, uint32_t b) {
    uint32_t d; asm("add.rn.f16x2 %0, %1, %2;" : "=r"(d) : "r"(a), "r"(b)); return d;
}
__device__ __forceinline__ uint32_t tanh2(uint32_t a) {
    uint32_t d; asm("tanh.approx.f16x2 %0, %1;" : "=r"(d) : "r"(a)); return d;
}
// f16 accumulators: c = {c0,c1} packed f16x2
__device__ __forceinline__ void mma_f16acc(uint32_t* c, uint32_t a0, uint32_t a1,
                                           uint32_t a2, uint32_t a3,
                                           uint32_t b0, uint32_t b1) {
    asm volatile(
        "mma.sync.aligned.m16n8k16.row.col.f16.f16.f16.f16 "
        "{%0,%1}, {%2,%3,%4,%5}, {%6,%7}, {%0,%1};"
        : "+r"(c[0]), "+r"(c[1])
        : "r"(a0), "r"(a1), "r"(a2), "r"(a3), "r"(b0), "r"(b1));
}

// ---------------- prep kernel: 512 threads, multi-row passes ----------------
#define PREP_SMEM (256 * 129 * 4 + 1056 * 4)
#define NUNITS_PREP 576        // 512 input row-pairs + 64 rel groups-of-4

__global__ __launch_bounds__(512, 1)
void prep_kernel(const float* __restrict__ inputs,
                 const float* __restrict__ Wh_w,
                 const float* __restrict__ Wh_b,
                 const float* __restrict__ rel_pos)
{
    extern __shared__ float sm[];
    float* Wsm = sm;                  // [k_glob][h] stride 129
    float* xs  = sm + 256 * 129;
    const int tid = threadIdx.x;

    for (int idx = tid; idx < 128 * 256; idx += 512) {
        int h = idx >> 8;
        int k = idx & 255;
        Wsm[k * 129 + h] = Wh_w[idx];
    }
    __syncthreads();

    for (int u = blockIdx.x; u < NUNITS_PREP; u += gridDim.x) {
        if (u < 512) {
            const int r0 = u * 2;
            if (tid < 256) {
                int row = tid >> 7, k = tid & 127;
                int l = (r0 + row) & (LL - 1);
                int i2 = k >> 1;
                float freq = exp2f(-(float)(2 * i2) * (13.287712379549449f / 128.0f));
                float ang = (float)l * freq;
                float em = (k & 1) ? cosf(ang) : sinf(ang);
                xs[row * 132 + k] = inputs[(r0 + row) * 128 + k] + em;
            }
            __syncthreads();
            {
                int row  = tid >> 8;
                int half = (tid >> 7) & 1;
                int h    = tid & 127;
                float s = half ? 0.0f : Wh_b[h];
                const float* wb = Wsm + half * 128 * 129 + h;
                const float* xr = xs + row * 132;
                #pragma unroll 8
                for (int kk = 0; kk < 128; kk++) s += xr[kk] * wb[kk * 129];
                const int r = r0 + row;
                if (half) g_pjh[r * 128 + permh(h)] = __float2half(s);
                else      g_piP[r * 128 + permh(h)] = __float2half(s);
            }
            __syncthreads();
        } else {
            const int g = u - 512;
            for (int idx = tid; idx < 1024; idx += 512) {
                int row = idx >> 8, k = idx & 255;
                int d = g * 4 + row;
                xs[row * 264 + k] = (d < 255)
                    ? rel_pos[(size_t)(127 * 512 + d) * 256 + k] : 0.0f;
            }
            __syncthreads();
            {
                int row = tid >> 7;
                int h   = tid & 127;
                int d = g * 4 + row;
                float s = 0.0f;
                const float* xr = xs + row * 264;
                const float* wb = Wsm + h;
                #pragma unroll 8
                for (int k = 0; k < 256; k++) s += xr[k] * wb[k * 129];
                if (d < 255) g_Rh[d * 128 + permh(h)] = __float2half(s);
            }
            __syncthreads();
        }
    }
}

// ---------------- main kernel smem layout (bytes) ----------------
#define ROWB 288
#define OFF_WOB  0                          // 64 f32 = 256B
#define OFF_MASK 256                        // 1024 f32 = 4096B
#define OFF_B    4352                       // 28 dense slots * 512 = 14336
#define OFF_R    18688                      // 255*288 = 73440
#define SMEM_MAIN (OFF_R + 255 * ROWB + 16)

__global__ __launch_bounds__(512, 1)
void main_kernel(const float* __restrict__ mask,
                 const float* __restrict__ Wo_w,
                 const float* __restrict__ Wo_b,
                 float* __restrict__ out)
{
    extern __shared__ char smc[];
    const int tid  = threadIdx.x;
    const int w    = tid >> 5;
    const int lane = tid & 31;
    const int gid  = lane >> 2;        // mma row group 0..7
    const int q2   = (lane & 3) << 1;  // 0,2,4,6
    const int grp  = w >> 3;           // 0/1 -> tile 4q+2grp+t
    const int wg   = w & 7;
    const int jl   = (wg << 4) + gid;
    const int jh   = jl + 8;

    // ---- stage wob + mask + R + B (once; only sync in kernel) ----
    if (tid < 64) ((float*)(smc + OFF_WOB))[tid] = (tid < CC) ? Wo_b[tid] : 0.0f;
    for (int idx = tid; idx < BB * LL; idx += 512)
        ((float*)(smc + OFF_MASK))[idx] = mask[idx];
    for (int idx = tid; idx < 255 * 16; idx += 512) {
        const int row = idx >> 4;
        const int t   = idx & 15;
        *(uint4*)(smc + OFF_R + row * ROWB + t * 16) = ((const uint4*)g_Rh)[idx];
    }
    for (int s = w; s < 28; s += 16) {
        const int kp = s / 7;
        const int n  = s % 7;
        const int c  = n * 8 + gid;
        uint32_t b00 = 0, b01 = 0, b10 = 0, b11 = 0;
        if (c < CC) {
            const float* wp = Wo_w + c * 128 + kp * 32 + q2;
            b00 = pack_f16x2(wp[0],  wp[1]);
            b01 = pack_f16x2(wp[8],  wp[9]);
            b10 = pack_f16x2(wp[16], wp[17]);
            b11 = pack_f16x2(wp[24], wp[25]);
        }
        *(uint4*)(smc + OFF_B + (s * 32 + lane) * 16) = make_uint4(b00, b01, b10, b11);
    }
    __syncthreads();

    const float* maskS = (const float*)(smc + OFF_MASK);
    const float* wobp  = (const float*)(smc + OFF_WOB);

    // ---- quad range ----
    const int q0 = (int)(((long long)blockIdx.x * NQUADS) / gridDim.x);
    const int q1 = (int)(((long long)(blockIdx.x + 1) * NQUADS) / gridDim.x);

    int prev_bjt = -1;
    int b = 0, j0 = 0, jg_lo = 0, jg_hi = 0;
    float mclo = 0.f, mchi = 0.f, adclo = 0.f, adchi = 0.f;
    uint2 pjl0[4], pjl1[4], pjh0[4], pjh1[4];   // pj fragment share in regs

    uint32_t acc[2][NBLK][2];
    #pragma unroll
    for (int t = 0; t < 2; t++)
        #pragma unroll
        for (int n = 0; n < NBLK; n++) { acc[t][n][0] = 0u; acc[t][n][1] = 0u; }

    for (int q = q0; q < q1; q++) {
        const int bjt = q >> 7;
        if (bjt != prev_bjt) {
            prev_bjt = bjt;
            b  = bjt >> 2;
            j0 = (bjt & 3) << 7;
            jg_lo = j0 + jl;
            jg_hi = j0 + jh;
            const char* rlo = (const char*)g_pjh + (size_t)((b << 9) + jg_lo) * 256 + q2 * 4;
            const char* rhi = (const char*)g_pjh + (size_t)((b << 9) + jg_hi) * 256 + q2 * 4;
            #pragma unroll
            for (int kp = 0; kp < 4; kp++) {
                pjl0[kp] = *(const uint2*)(rlo + kp * 64);
                pjl1[kp] = *(const uint2*)(rlo + kp * 64 + 32);
                pjh0[kp] = *(const uint2*)(rhi + kp * 64);
                pjh1[kp] = *(const uint2*)(rhi + kp * 64 + 32);
            }
            mclo = maskS[(b << 9) + jg_lo];
            mchi = maskS[(b << 9) + jg_hi];
            adclo = -NEGV * (1.0f - mclo);
            adchi = -NEGV * (1.0f - mchi);
        }
        const int i0 = ((q & 127) << 2) + (grp << 1);

        // per-t row-dependent smem/global offsets
        uint32_t rl_off[2], rh_off[2];
        const char* pip[2];
        #pragma unroll
        for (int t = 0; t < 2; t++) {
            const int i = i0 + t;
            int dlo = jg_lo - i; dlo = dlo < -127 ? -127 : (dlo > 127 ? 127 : dlo);
            int dhi = jg_hi - i; dhi = dhi < -127 ? -127 : (dhi > 127 ? 127 : dhi);
            rl_off[t] = (uint32_t)((dlo + 127) * ROWB) + q2 * 4;
            rh_off[t] = (uint32_t)((dhi + 127) * ROWB) + q2 * 4;
            pip[t] = (const char*)g_piP + (size_t)((b << 9) + i) * 256 + q2 * 4;
        }

        #pragma unroll
        for (int kp = 0; kp < 4; kp++) {
            uint32_t A[2][8];
            #pragma unroll
            for (int t = 0; t < 2; t++) {
                const uint2 pi0 = *(const uint2*)(pip[t] + kp * 64);
                const uint2 pi1 = *(const uint2*)(pip[t] + kp * 64 + 32);
                const uint2 rl0 = *(const uint2*)(smc + OFF_R + rl_off[t] + kp * 64);
                const uint2 rl1 = *(const uint2*)(smc + OFF_R + rl_off[t] + kp * 64 + 32);
                const uint2 rh0 = *(const uint2*)(smc + OFF_R + rh_off[t] + kp * 64);
                const uint2 rh1 = *(const uint2*)(smc + OFF_R + rh_off[t] + kp * 64 + 32);
                A[t][0] = tanh2(hadd2(hadd2(pi0.x, pjl0[kp].x), rl0.x));
                A[t][1] = tanh2(hadd2(hadd2(pi0.x, pjh0[kp].x), rh0.x));
                A[t][2] = tanh2(hadd2(hadd2(pi0.y, pjl0[kp].y), rl0.y));
                A[t][3] = tanh2(hadd2(hadd2(pi0.y, pjh0[kp].y), rh0.y));
                A[t][4] = tanh2(hadd2(hadd2(pi1.x, pjl1[kp].x), rl1.x));
                A[t][5] = tanh2(hadd2(hadd2(pi1.x, pjh1[kp].x), rh1.x));
                A[t][6] = tanh2(hadd2(hadd2(pi1.y, pjl1[kp].y), rl1.y));
                A[t][7] = tanh2(hadd2(hadd2(pi1.y, pjh1[kp].y), rh1.y));
            }
            #pragma unroll
            for (int n = 0; n < NBLK; n++) {
                const uint4 bb = *(const uint4*)(smc + OFF_B + ((kp * 7 + n) * 32 + lane) * 16);
                #pragma unroll
                for (int t = 0; t < 2; t++) {
                    mma_f16acc(acc[t][n], A[t][0], A[t][1], A[t][2], A[t][3], bb.x, bb.y);
                    mma_f16acc(acc[t][n], A[t][4], A[t][5], A[t][6], A[t][7], bb.z, bb.w);
                }
            }
        }

        // ---- epilogue per t ----
        #pragma unroll
        for (int t = 0; t < 2; t++) {
            const int i = i0 + t;
            const float mr = maskS[(b << 9) + i];
            const float addr_ = -NEGV * (1.0f - mr);
            const float trilo = (jg_lo < i) ? NEGV : 0.0f;
            const float trihi = (jg_hi < i) ? NEGV : 0.0f;
            float* ob = out + (size_t)b * CC * LL * LL + (size_t)i * LL;
            #pragma unroll
            for (int n = 0; n < NBLK; n++) {
                const int c0 = n * 8 + q2;
                const float2 wv = *(const float2*)(wobp + c0);
                const float2 lo = __half22float2(*(__half2*)&acc[t][n][0]);
                const float2 hi = __half22float2(*(__half2*)&acc[t][n][1]);
                float v0 = (lo.x + wv.x) * mr + addr_;
                float v1 = (lo.y + wv.y) * mr + addr_;
                float v2 = (hi.x + wv.x) * mr + addr_;
                float v3 = (hi.y + wv.y) * mr + addr_;
                v0 = v0 * mclo + adclo - trilo;
                v1 = v1 * mclo + adclo - trilo;
                v2 = v2 * mchi + adchi - trihi;
                v3 = v3 * mchi + adchi - trihi;
                if (c0 < CC) {
                    ob[(size_t)c0 * (LL * LL) + jg_lo] = v0;
                    ob[(size_t)c0 * (LL * LL) + jg_hi] = v2;
                }
                if (c0 + 1 < CC) {
                    ob[(size_t)(c0 + 1) * (LL * LL) + jg_lo] = v1;
                    ob[(size_t)(c0 + 1) * (LL * LL) + jg_hi] = v3;
                }
                acc[t][n][0] = 0u; acc[t][n][1] = 0u;
            }
        }
    }
}

// ---------------- launch ----------------
extern "C" void kernel_launch(void* const* d_in, const int* in_sizes, int n_in,
                              void* d_out, int out_size)
{
    const float* inputs = (const float*)d_in[0];
    const float* mask   = (const float*)d_in[1];
    const float* Wh_w   = (const float*)d_in[2];
    const float* Wh_b   = (const float*)d_in[3];
    const float* Wo_w   = (const float*)d_in[4];
    const float* Wo_b   = (const float*)d_in[5];
    const float* rel    = (const float*)d_in[6];
    float* out = (float*)d_out;

    cudaFuncSetAttribute(prep_kernel, cudaFuncAttributeMaxDynamicSharedMemorySize, PREP_SMEM);
    cudaFuncSetAttribute(main_kernel, cudaFuncAttributeMaxDynamicSharedMemorySize, SMEM_MAIN);

    prep_kernel<<<NSM, 512, PREP_SMEM>>>(inputs, Wh_w, Wh_b, rel);
    main_kernel<<<NSM, 512, SMEM_MAIN>>>(mask, Wo_w, Wo_b, out);
}